// round 1
// baseline (speedup 1.0000x reference)
#include <cuda_runtime.h>
#include <cuda_bf16.h>

#define N_LEVELS 20
#define LOG2T 19
#define TSIZE (1 << LOG2T)
#define TMASK (TSIZE - 1)
#define PRIME_Y 2654435761u
#define PRIME_Z 805459861u

// res[i] = int(16 * 1.39**i); verified against double-precision pow, none near
// an integer boundary (closest is 222.97).
__constant__ float c_res[N_LEVELS] = {
    16.f, 22.f, 30.f, 42.f, 59.f, 83.f, 115.f, 160.f, 222.f, 309.f,
    430.f, 598.f, 832.f, 1156.f, 1608.f, 2235.f, 3107.f, 4318.f, 6003.f, 8344.f
};

__global__ void __launch_bounds__(256)
hash_encode_kernel(const float* __restrict__ x,
                   const float* __restrict__ tables,
                   float* __restrict__ out,
                   int n)
{
    int p = blockIdx.x * blockDim.x + threadIdx.x;
    if (p >= n) return;

    float px = x[3 * p + 0];
    float py = x[3 * p + 1];
    float pz = x[3 * p + 2];

    float2* __restrict__ out2 = reinterpret_cast<float2*>(out) + (size_t)p * N_LEVELS;

#pragma unroll
    for (int l = 0; l < N_LEVELS; ++l) {
        const float res = c_res[l];
        const float2* __restrict__ tab =
            reinterpret_cast<const float2*>(tables) + (size_t)l * TSIZE;

        float xs = px * res;
        float ys = py * res;
        float zs = pz * res;
        float fx = floorf(xs);
        float fy = floorf(ys);
        float fz = floorf(zs);
        float wx = xs - fx;
        float wy = ys - fy;
        float wz = zs - fz;

        unsigned vx = (unsigned)(int)fx;
        unsigned vy = (unsigned)(int)fy;
        unsigned vz = (unsigned)(int)fz;

        // Partial hashes shared across corner pairs.
        unsigned hy0 = vy * PRIME_Y;
        unsigned hy1 = (vy + 1u) * PRIME_Y;
        unsigned hz0 = vz * PRIME_Z;
        unsigned hz1 = (vz + 1u) * PRIME_Z;
        unsigned vx1 = vx + 1u;

        unsigned s00 = hy0 ^ hz0;   // (j=0,k=0)
        unsigned s01 = hy0 ^ hz1;   // (j=0,k=1)
        unsigned s10 = hy1 ^ hz0;   // (j=1,k=0)
        unsigned s11 = hy1 ^ hz1;   // (j=1,k=1)

        // Corner order matches OFFSETS = [i*4 + j*2 + k]
        float2 e0 = __ldg(&tab[(vx  ^ s00) & TMASK]);  // (0,0,0)
        float2 e1 = __ldg(&tab[(vx  ^ s01) & TMASK]);  // (0,0,1)
        float2 e2 = __ldg(&tab[(vx  ^ s10) & TMASK]);  // (0,1,0)
        float2 e3 = __ldg(&tab[(vx  ^ s11) & TMASK]);  // (0,1,1)
        float2 e4 = __ldg(&tab[(vx1 ^ s00) & TMASK]);  // (1,0,0)
        float2 e5 = __ldg(&tab[(vx1 ^ s01) & TMASK]);  // (1,0,1)
        float2 e6 = __ldg(&tab[(vx1 ^ s10) & TMASK]);  // (1,1,0)
        float2 e7 = __ldg(&tab[(vx1 ^ s11) & TMASK]);  // (1,1,1)

        float omx = 1.f - wx;
        float omy = 1.f - wy;
        float omz = 1.f - wz;

        // Feature 0
        float c00a = e0.x * omx + e4.x * wx;
        float c01a = e1.x * omx + e5.x * wx;
        float c10a = e2.x * omx + e6.x * wx;
        float c11a = e3.x * omx + e7.x * wx;
        float c0a  = c00a * omy + c10a * wy;
        float c1a  = c01a * omy + c11a * wy;
        float ra   = c0a * omz + c1a * wz;

        // Feature 1
        float c00b = e0.y * omx + e4.y * wx;
        float c01b = e1.y * omx + e5.y * wx;
        float c10b = e2.y * omx + e6.y * wx;
        float c11b = e3.y * omx + e7.y * wx;
        float c0b  = c00b * omy + c10b * wy;
        float c1b  = c01b * omy + c11b * wy;
        float rb   = c0b * omz + c1b * wz;

        out2[l] = make_float2(ra, rb);
    }
}

extern "C" void kernel_launch(void* const* d_in, const int* in_sizes, int n_in,
                              void* d_out, int out_size)
{
    const float* x      = (const float*)d_in[0];
    const float* tables = (const float*)d_in[1];
    float* out          = (float*)d_out;

    int n = in_sizes[0] / 3;  // (N, 3) points
    int threads = 256;
    int blocks = (n + threads - 1) / threads;
    hash_encode_kernel<<<blocks, threads>>>(x, tables, out, n);
}

// round 3
// speedup vs baseline: 1.1622x; 1.1622x over previous
#include <cuda_runtime.h>
#include <cuda_bf16.h>

#define N_LEVELS 20
#define LOG2T 19
#define TSIZE (1 << LOG2T)
#define TMASK (TSIZE - 1)
#define PRIME_Y 2654435761u
#define PRIME_Z 805459861u

// res[i] = int(16 * 1.39**i); verified against double-precision pow.
__constant__ float c_res[N_LEVELS] = {
    16.f, 22.f, 30.f, 42.f, 59.f, 83.f, 115.f, 160.f, 222.f, 309.f,
    430.f, 598.f, 832.f, 1156.f, 1608.f, 2235.f, 3107.f, 4318.f, 6003.f, 8344.f
};

// One level's bilinear/trilinear blend. Uses the "paired corner" trick:
// hash(vx, y, z) = vx ^ s  (x enters un-multiplied), so for even vx the two
// x-corners (vx, vx+1) land on adjacent table entries {2m, 2m+1} -> one
// 16B-aligned float4 load serves both. For odd vx a second (predicated-address)
// float2 load fetches the x=1 corner; even-vx lanes point that load at
// table[0], which warp-dedups to ~1 sector.
__device__ __forceinline__ float2 encode_level(float px, float py, float pz,
                                               const float2* __restrict__ tab,
                                               float res)
{
    const float4* __restrict__ tab4 = reinterpret_cast<const float4*>(tab);

    float xs = px * res, ys = py * res, zs = pz * res;
    float fx = floorf(xs), fy = floorf(ys), fz = floorf(zs);
    float wx = xs - fx, wy = ys - fy, wz = zs - fz;

    unsigned vx = (unsigned)(int)fx;
    unsigned vy = (unsigned)(int)fy;
    unsigned vz = (unsigned)(int)fz;

    unsigned hy0 = vy * PRIME_Y;
    unsigned hy1 = (vy + 1u) * PRIME_Y;
    unsigned hz0 = vz * PRIME_Z;
    unsigned hz1 = (vz + 1u) * PRIME_Z;

    unsigned s00 = hy0 ^ hz0;
    unsigned s01 = hy0 ^ hz1;
    unsigned s10 = hy1 ^ hz0;
    unsigned s11 = hy1 ^ hz1;

    unsigned vx1 = vx + 1u;
    bool odd = (vx & 1u) != 0u;

    // x=0 corner indices
    unsigned i00 = (vx ^ s00) & TMASK;
    unsigned i01 = (vx ^ s01) & TMASK;
    unsigned i10 = (vx ^ s10) & TMASK;
    unsigned i11 = (vx ^ s11) & TMASK;

    // Aligned pair loads (always contain the x=0 corner; for even vx also x=1)
    float4 q00 = __ldg(&tab4[i00 >> 1]);
    float4 q01 = __ldg(&tab4[i01 >> 1]);
    float4 q10 = __ldg(&tab4[i10 >> 1]);
    float4 q11 = __ldg(&tab4[i11 >> 1]);

    // x=1 corner indices (only meaningful when vx odd); even lanes -> entry 0
    unsigned j00 = odd ? ((vx1 ^ s00) & TMASK) : 0u;
    unsigned j01 = odd ? ((vx1 ^ s01) & TMASK) : 0u;
    unsigned j10 = odd ? ((vx1 ^ s10) & TMASK) : 0u;
    unsigned j11 = odd ? ((vx1 ^ s11) & TMASK) : 0u;

    float2 g00 = __ldg(&tab[j00]);
    float2 g01 = __ldg(&tab[j01]);
    float2 g10 = __ldg(&tab[j10]);
    float2 g11 = __ldg(&tab[j11]);

    // Split pairs into (corner x=0, neighbor)
    float2 lo00 = make_float2(q00.x, q00.y), hi00 = make_float2(q00.z, q00.w);
    float2 lo01 = make_float2(q01.x, q01.y), hi01 = make_float2(q01.z, q01.w);
    float2 lo10 = make_float2(q10.x, q10.y), hi10 = make_float2(q10.z, q10.w);
    float2 lo11 = make_float2(q11.x, q11.y), hi11 = make_float2(q11.z, q11.w);

    bool p00 = (i00 & 1u) != 0u;
    bool p01 = (i01 & 1u) != 0u;
    bool p10 = (i10 & 1u) != 0u;
    bool p11 = (i11 & 1u) != 0u;

    float2 e0 = p00 ? hi00 : lo00;          // corner (0,0,0)
    float2 e1 = p01 ? hi01 : lo01;          // corner (0,0,1)
    float2 e2 = p10 ? hi10 : lo10;          // corner (0,1,0)
    float2 e3 = p11 ? hi11 : lo11;          // corner (0,1,1)

    float2 n00 = p00 ? lo00 : hi00;         // entry i00^1 (valid x=1 if even)
    float2 n01 = p01 ? lo01 : hi01;
    float2 n10 = p10 ? lo10 : hi10;
    float2 n11 = p11 ? lo11 : hi11;

    float2 e4 = odd ? g00 : n00;            // corner (1,0,0)
    float2 e5 = odd ? g01 : n01;            // corner (1,0,1)
    float2 e6 = odd ? g10 : n10;            // corner (1,1,0)
    float2 e7 = odd ? g11 : n11;            // corner (1,1,1)

    float omx = 1.f - wx, omy = 1.f - wy, omz = 1.f - wz;

    float c00a = e0.x * omx + e4.x * wx;
    float c01a = e1.x * omx + e5.x * wx;
    float c10a = e2.x * omx + e6.x * wx;
    float c11a = e3.x * omx + e7.x * wx;
    float c0a  = c00a * omy + c10a * wy;
    float c1a  = c01a * omy + c11a * wy;
    float ra   = c0a * omz + c1a * wz;

    float c00b = e0.y * omx + e4.y * wx;
    float c01b = e1.y * omx + e5.y * wx;
    float c10b = e2.y * omx + e6.y * wx;
    float c11b = e3.y * omx + e7.y * wx;
    float c0b  = c00b * omy + c10b * wy;
    float c1b  = c01b * omy + c11b * wy;
    float rb   = c0b * omz + c1b * wz;

    return make_float2(ra, rb);
}

__global__ void __launch_bounds__(256)
hash_encode_kernel(const float* __restrict__ x,
                   const float* __restrict__ tables,
                   float* __restrict__ out,
                   int n)
{
    int p = blockIdx.x * blockDim.x + threadIdx.x;
    if (p >= n) return;

    float px = x[3 * p + 0];
    float py = x[3 * p + 1];
    float pz = x[3 * p + 2];

    float4* __restrict__ out4 =
        reinterpret_cast<float4*>(out) + (size_t)p * (N_LEVELS / 2);

#pragma unroll
    for (int l = 0; l < N_LEVELS; l += 2) {
        const float2* __restrict__ tabA =
            reinterpret_cast<const float2*>(tables) + (size_t)l * TSIZE;
        const float2* __restrict__ tabB =
            reinterpret_cast<const float2*>(tables) + (size_t)(l + 1) * TSIZE;

        float2 rA = encode_level(px, py, pz, tabA, c_res[l]);
        float2 rB = encode_level(px, py, pz, tabB, c_res[l + 1]);

        // Streaming store: keep L2 for the hash tables, not the output stream.
        __stcs(&out4[l >> 1], make_float4(rA.x, rA.y, rB.x, rB.y));
    }
}

extern "C" void kernel_launch(void* const* d_in, const int* in_sizes, int n_in,
                              void* d_out, int out_size)
{
    const float* x      = (const float*)d_in[0];
    const float* tables = (const float*)d_in[1];
    float* out          = (float*)d_out;

    int n = in_sizes[0] / 3;  // (N, 3) points
    int threads = 256;
    int blocks = (n + threads - 1) / threads;
    hash_encode_kernel<<<blocks, threads>>>(x, tables, out, n);
}

// round 5
// speedup vs baseline: 1.2785x; 1.1001x over previous
#include <cuda_runtime.h>
#include <cuda_bf16.h>

#define N_LEVELS 20
#define LOG2T 19
#define TSIZE (1 << LOG2T)
#define TMASK (TSIZE - 1)
#define PRIME_Y 2654435761u
#define PRIME_Z 805459861u

#define CAP       (1 << 20)     // max points supported by sort path
#define KEY_BITS  5             // per-dim
#define GRID_DIM  (1 << KEY_BITS)
#define NBUCKETS  (1 << (3 * KEY_BITS))   // 32768

// Static scratch (no allocation allowed): 16MB point buffer + histograms.
__device__ float4   g_scratch[CAP];
__device__ unsigned g_hist[NBUCKETS];
__device__ unsigned g_cursor[NBUCKETS];

// res[i] = int(16 * 1.39**i); verified against double-precision pow.
__constant__ float c_res[N_LEVELS] = {
    16.f, 22.f, 30.f, 42.f, 59.f, 83.f, 115.f, 160.f, 222.f, 309.f,
    430.f, 598.f, 832.f, 1156.f, 1608.f, 2235.f, 3107.f, 4318.f, 6003.f, 8344.f
};

__device__ __forceinline__ int bucket_key(float px, float py, float pz)
{
    int ix = min(GRID_DIM - 1, (int)(px * (float)GRID_DIM));
    int iy = min(GRID_DIM - 1, (int)(py * (float)GRID_DIM));
    int iz = min(GRID_DIM - 1, (int)(pz * (float)GRID_DIM));
    return (ix << (2 * KEY_BITS)) | (iy << KEY_BITS) | iz;
}

// ---------------- sort pipeline ----------------

__global__ void zero_hist_kernel()
{
    int i = blockIdx.x * blockDim.x + threadIdx.x;
    if (i < NBUCKETS) g_hist[i] = 0u;
}

__global__ void hist_kernel(const float* __restrict__ x, int n)
{
    int p = blockIdx.x * blockDim.x + threadIdx.x;
    if (p >= n) return;
    int k = bucket_key(x[3 * p], x[3 * p + 1], x[3 * p + 2]);
    atomicAdd(&g_hist[k], 1u);
}

// One block, 1024 threads; each thread owns 32 consecutive buckets.
__global__ void __launch_bounds__(1024)
prefix_kernel()
{
    __shared__ unsigned part[1024];
    int t = threadIdx.x;

    unsigned local[NBUCKETS / 1024];
    unsigned s = 0;
#pragma unroll
    for (int j = 0; j < NBUCKETS / 1024; ++j) {
        local[j] = g_hist[t * (NBUCKETS / 1024) + j];
        s += local[j];
    }
    part[t] = s;
    __syncthreads();

    // Hillis-Steele inclusive scan over 1024 partials.
    for (int off = 1; off < 1024; off <<= 1) {
        unsigned v = (t >= off) ? part[t - off] : 0u;
        __syncthreads();
        part[t] += v;
        __syncthreads();
    }

    unsigned run = (t > 0) ? part[t - 1] : 0u;
#pragma unroll
    for (int j = 0; j < NBUCKETS / 1024; ++j) {
        g_cursor[t * (NBUCKETS / 1024) + j] = run;
        run += local[j];
    }
}

__global__ void scatter_kernel(const float* __restrict__ x, int n)
{
    int p = blockIdx.x * blockDim.x + threadIdx.x;
    if (p >= n) return;
    float px = x[3 * p], py = x[3 * p + 1], pz = x[3 * p + 2];
    int k = bucket_key(px, py, pz);
    unsigned pos = atomicAdd(&g_cursor[k], 1u);
    g_scratch[pos] = make_float4(px, py, pz, __int_as_float(p));
}

// ---------------- encode ----------------

// Paired-corner trick: hash(vx,y,z) = vx ^ s, so the 16B-aligned table pair
// {i&~1, i|1} holds the entries for x-coords {vx, vx^1}. For even vx that IS
// (vx, vx+1); for odd vx a second load fetches vx+1 (even lanes -> tab[0],
// which warp-dedups).
__device__ __forceinline__ float2 encode_level(float px, float py, float pz,
                                               const float2* __restrict__ tab,
                                               float res)
{
    const float4* __restrict__ tab4 = reinterpret_cast<const float4*>(tab);

    float xs = px * res, ys = py * res, zs = pz * res;
    float fx = floorf(xs), fy = floorf(ys), fz = floorf(zs);
    float wx = xs - fx, wy = ys - fy, wz = zs - fz;

    unsigned vx = (unsigned)(int)fx;
    unsigned vy = (unsigned)(int)fy;
    unsigned vz = (unsigned)(int)fz;

    unsigned hy0 = vy * PRIME_Y;
    unsigned hy1 = (vy + 1u) * PRIME_Y;
    unsigned hz0 = vz * PRIME_Z;
    unsigned hz1 = (vz + 1u) * PRIME_Z;

    unsigned s00 = hy0 ^ hz0;
    unsigned s01 = hy0 ^ hz1;
    unsigned s10 = hy1 ^ hz0;
    unsigned s11 = hy1 ^ hz1;

    unsigned vx1 = vx + 1u;
    bool odd = (vx & 1u) != 0u;

    unsigned i00 = (vx ^ s00) & TMASK;
    unsigned i01 = (vx ^ s01) & TMASK;
    unsigned i10 = (vx ^ s10) & TMASK;
    unsigned i11 = (vx ^ s11) & TMASK;

    float4 q00 = __ldg(&tab4[i00 >> 1]);
    float4 q01 = __ldg(&tab4[i01 >> 1]);
    float4 q10 = __ldg(&tab4[i10 >> 1]);
    float4 q11 = __ldg(&tab4[i11 >> 1]);

    unsigned j00 = odd ? ((vx1 ^ s00) & TMASK) : 0u;
    unsigned j01 = odd ? ((vx1 ^ s01) & TMASK) : 0u;
    unsigned j10 = odd ? ((vx1 ^ s10) & TMASK) : 0u;
    unsigned j11 = odd ? ((vx1 ^ s11) & TMASK) : 0u;

    float2 g00 = __ldg(&tab[j00]);
    float2 g01 = __ldg(&tab[j01]);
    float2 g10 = __ldg(&tab[j10]);
    float2 g11 = __ldg(&tab[j11]);

    float2 lo00 = make_float2(q00.x, q00.y), hi00 = make_float2(q00.z, q00.w);
    float2 lo01 = make_float2(q01.x, q01.y), hi01 = make_float2(q01.z, q01.w);
    float2 lo10 = make_float2(q10.x, q10.y), hi10 = make_float2(q10.z, q10.w);
    float2 lo11 = make_float2(q11.x, q11.y), hi11 = make_float2(q11.z, q11.w);

    bool p00 = (i00 & 1u) != 0u;
    bool p01 = (i01 & 1u) != 0u;
    bool p10 = (i10 & 1u) != 0u;
    bool p11 = (i11 & 1u) != 0u;

    float2 e0 = p00 ? hi00 : lo00;
    float2 e1 = p01 ? hi01 : lo01;
    float2 e2 = p10 ? hi10 : lo10;
    float2 e3 = p11 ? hi11 : lo11;

    float2 n00 = p00 ? lo00 : hi00;
    float2 n01 = p01 ? lo01 : hi01;
    float2 n10 = p10 ? lo10 : hi10;
    float2 n11 = p11 ? lo11 : hi11;

    float2 e4 = odd ? g00 : n00;
    float2 e5 = odd ? g01 : n01;
    float2 e6 = odd ? g10 : n10;
    float2 e7 = odd ? g11 : n11;

    float omx = 1.f - wx, omy = 1.f - wy, omz = 1.f - wz;

    float c00a = e0.x * omx + e4.x * wx;
    float c01a = e1.x * omx + e5.x * wx;
    float c10a = e2.x * omx + e6.x * wx;
    float c11a = e3.x * omx + e7.x * wx;
    float c0a  = c00a * omy + c10a * wy;
    float c1a  = c01a * omy + c11a * wy;
    float ra   = c0a * omz + c1a * wz;

    float c00b = e0.y * omx + e4.y * wx;
    float c01b = e1.y * omx + e5.y * wx;
    float c10b = e2.y * omx + e6.y * wx;
    float c11b = e3.y * omx + e7.y * wx;
    float c0b  = c00b * omy + c10b * wy;
    float c1b  = c01b * omy + c11b * wy;
    float rb   = c0b * omz + c1b * wz;

    return make_float2(ra, rb);
}

__global__ void __launch_bounds__(256)
encode_sorted_kernel(const float* __restrict__ tables,
                     float* __restrict__ out,
                     int n)
{
    int i = blockIdx.x * blockDim.x + threadIdx.x;
    if (i >= n) return;

    float4 s = g_scratch[i];
    float px = s.x, py = s.y, pz = s.z;
    int   id = __float_as_int(s.w);

    float4* __restrict__ out4 =
        reinterpret_cast<float4*>(out) + (size_t)id * (N_LEVELS / 2);

#pragma unroll
    for (int l = 0; l < N_LEVELS; l += 2) {
        const float2* __restrict__ tabA =
            reinterpret_cast<const float2*>(tables) + (size_t)l * TSIZE;
        const float2* __restrict__ tabB =
            reinterpret_cast<const float2*>(tables) + (size_t)(l + 1) * TSIZE;

        float2 rA = encode_level(px, py, pz, tabA, c_res[l]);
        float2 rB = encode_level(px, py, pz, tabB, c_res[l + 1]);

        __stcs(&out4[l >> 1], make_float4(rA.x, rA.y, rB.x, rB.y));
    }
}

// Fallback (n > CAP): encode directly from x in input order.
__global__ void __launch_bounds__(256)
encode_direct_kernel(const float* __restrict__ x,
                     const float* __restrict__ tables,
                     float* __restrict__ out,
                     int n)
{
    int p = blockIdx.x * blockDim.x + threadIdx.x;
    if (p >= n) return;

    float px = x[3 * p], py = x[3 * p + 1], pz = x[3 * p + 2];
    float4* __restrict__ out4 =
        reinterpret_cast<float4*>(out) + (size_t)p * (N_LEVELS / 2);

#pragma unroll
    for (int l = 0; l < N_LEVELS; l += 2) {
        const float2* __restrict__ tabA =
            reinterpret_cast<const float2*>(tables) + (size_t)l * TSIZE;
        const float2* __restrict__ tabB =
            reinterpret_cast<const float2*>(tables) + (size_t)(l + 1) * TSIZE;

        float2 rA = encode_level(px, py, pz, tabA, c_res[l]);
        float2 rB = encode_level(px, py, pz, tabB, c_res[l + 1]);

        __stcs(&out4[l >> 1], make_float4(rA.x, rA.y, rB.x, rB.y));
    }
}

extern "C" void kernel_launch(void* const* d_in, const int* in_sizes, int n_in,
                              void* d_out, int out_size)
{
    const float* x      = (const float*)d_in[0];
    const float* tables = (const float*)d_in[1];
    float* out          = (float*)d_out;

    int n = in_sizes[0] / 3;
    int threads = 256;
    int blocks = (n + threads - 1) / threads;

    if (n <= CAP) {
        zero_hist_kernel<<<(NBUCKETS + 1023) / 1024, 1024>>>();
        hist_kernel<<<blocks, threads>>>(x, n);
        prefix_kernel<<<1, 1024>>>();
        scatter_kernel<<<blocks, threads>>>(x, n);
        encode_sorted_kernel<<<blocks, threads>>>(tables, out, n);
    } else {
        encode_direct_kernel<<<blocks, threads>>>(x, tables, out, n);
    }
}

// round 6
// speedup vs baseline: 1.2857x; 1.0056x over previous
#include <cuda_runtime.h>
#include <cuda_bf16.h>

#define N_LEVELS 20
#define LOG2T 19
#define TSIZE (1 << LOG2T)
#define TMASK (TSIZE - 1)
#define PRIME_Y 2654435761u
#define PRIME_Z 805459861u

#define CAP       (1 << 20)     // max points supported by sort path
#define KEY_BITS  5             // per-dim
#define GRID_DIM  (1 << KEY_BITS)
#define NBUCKETS  (1 << (3 * KEY_BITS))   // 32768

// Static scratch (no allocation allowed).
__device__ float4   g_scratch[CAP];
__device__ int      g_keys[CAP];
__device__ unsigned g_hist[NBUCKETS];
__device__ unsigned g_cursor[NBUCKETS];

// res[i] = int(16 * 1.39**i); verified against double-precision pow.
__constant__ float c_res[N_LEVELS] = {
    16.f, 22.f, 30.f, 42.f, 59.f, 83.f, 115.f, 160.f, 222.f, 309.f,
    430.f, 598.f, 832.f, 1156.f, 1608.f, 2235.f, 3107.f, 4318.f, 6003.f, 8344.f
};

__device__ __forceinline__ int bucket_key(float px, float py, float pz)
{
    int ix = min(GRID_DIM - 1, (int)(px * (float)GRID_DIM));
    int iy = min(GRID_DIM - 1, (int)(py * (float)GRID_DIM));
    int iz = min(GRID_DIM - 1, (int)(pz * (float)GRID_DIM));
    return (ix << (2 * KEY_BITS)) | (iy << KEY_BITS) | iz;
}

// ---------------- sort pipeline ----------------

__global__ void zero_hist_kernel()
{
    int i = blockIdx.x * blockDim.x + threadIdx.x;
    if (i < NBUCKETS) g_hist[i] = 0u;
}

// Compute key once, cache it, histogram it.
__global__ void hist_kernel(const float* __restrict__ x, int n)
{
    int p = blockIdx.x * blockDim.x + threadIdx.x;
    if (p >= n) return;
    int k = bucket_key(x[3 * p], x[3 * p + 1], x[3 * p + 2]);
    g_keys[p] = k;
    atomicAdd(&g_hist[k], 1u);
}

// One block, 1024 threads; each thread owns 32 consecutive buckets.
__global__ void __launch_bounds__(1024)
prefix_kernel()
{
    __shared__ unsigned part[1024];
    int t = threadIdx.x;

    unsigned local[NBUCKETS / 1024];
    unsigned s = 0;
#pragma unroll
    for (int j = 0; j < NBUCKETS / 1024; ++j) {
        local[j] = g_hist[t * (NBUCKETS / 1024) + j];
        s += local[j];
    }
    part[t] = s;
    __syncthreads();

    for (int off = 1; off < 1024; off <<= 1) {
        unsigned v = (t >= off) ? part[t - off] : 0u;
        __syncthreads();
        part[t] += v;
        __syncthreads();
    }

    unsigned run = (t > 0) ? part[t - 1] : 0u;
#pragma unroll
    for (int j = 0; j < NBUCKETS / 1024; ++j) {
        g_cursor[t * (NBUCKETS / 1024) + j] = run;
        run += local[j];
    }
}

__global__ void scatter_kernel(const float* __restrict__ x, int n)
{
    int p = blockIdx.x * blockDim.x + threadIdx.x;
    if (p >= n) return;
    int k = g_keys[p];
    float px = x[3 * p], py = x[3 * p + 1], pz = x[3 * p + 2];
    unsigned pos = atomicAdd(&g_cursor[k], 1u);
    g_scratch[pos] = make_float4(px, py, pz, __int_as_float(p));
}

// ---------------- encode ----------------

// Paired-corner trick: hash(vx,y,z) = vx ^ s, so the 16B-aligned table pair
// {i&~1, i|1} holds entries for x-coords {vx, vx^1}. Even vx: that is
// (vx, vx+1) -> one LDG.128 serves both corners. Odd vx: a predicated second
// load fetches vx+1 (even lanes inactive -> no extra L1 lines for them).
__device__ __forceinline__ float2 encode_level(float px, float py, float pz,
                                               const float2* __restrict__ tab,
                                               float res)
{
    const float4* __restrict__ tab4 = reinterpret_cast<const float4*>(tab);

    float xs = px * res, ys = py * res, zs = pz * res;
    float fx = floorf(xs), fy = floorf(ys), fz = floorf(zs);
    float wx = xs - fx, wy = ys - fy, wz = zs - fz;

    unsigned vx = (unsigned)(int)fx;
    unsigned vy = (unsigned)(int)fy;
    unsigned vz = (unsigned)(int)fz;

    unsigned hy0 = vy * PRIME_Y;
    unsigned hy1 = (vy + 1u) * PRIME_Y;
    unsigned hz0 = vz * PRIME_Z;
    unsigned hz1 = (vz + 1u) * PRIME_Z;

    unsigned s00 = hy0 ^ hz0;
    unsigned s01 = hy0 ^ hz1;
    unsigned s10 = hy1 ^ hz0;
    unsigned s11 = hy1 ^ hz1;

    unsigned vx1 = vx + 1u;
    bool odd = (vx & 1u) != 0u;

    unsigned i00 = (vx ^ s00) & TMASK;
    unsigned i01 = (vx ^ s01) & TMASK;
    unsigned i10 = (vx ^ s10) & TMASK;
    unsigned i11 = (vx ^ s11) & TMASK;

    float4 q00 = __ldg(&tab4[i00 >> 1]);
    float4 q01 = __ldg(&tab4[i01 >> 1]);
    float4 q10 = __ldg(&tab4[i10 >> 1]);
    float4 q11 = __ldg(&tab4[i11 >> 1]);

    // Predicated extra loads: only odd-vx lanes touch memory.
    float2 g00 = make_float2(0.f, 0.f);
    float2 g01 = g00, g10 = g00, g11 = g00;
    if (odd) {
        g00 = __ldg(&tab[(vx1 ^ s00) & TMASK]);
        g01 = __ldg(&tab[(vx1 ^ s01) & TMASK]);
        g10 = __ldg(&tab[(vx1 ^ s10) & TMASK]);
        g11 = __ldg(&tab[(vx1 ^ s11) & TMASK]);
    }

    float2 lo00 = make_float2(q00.x, q00.y), hi00 = make_float2(q00.z, q00.w);
    float2 lo01 = make_float2(q01.x, q01.y), hi01 = make_float2(q01.z, q01.w);
    float2 lo10 = make_float2(q10.x, q10.y), hi10 = make_float2(q10.z, q10.w);
    float2 lo11 = make_float2(q11.x, q11.y), hi11 = make_float2(q11.z, q11.w);

    bool p00 = (i00 & 1u) != 0u;
    bool p01 = (i01 & 1u) != 0u;
    bool p10 = (i10 & 1u) != 0u;
    bool p11 = (i11 & 1u) != 0u;

    float2 e0 = p00 ? hi00 : lo00;
    float2 e1 = p01 ? hi01 : lo01;
    float2 e2 = p10 ? hi10 : lo10;
    float2 e3 = p11 ? hi11 : lo11;

    float2 n00 = p00 ? lo00 : hi00;
    float2 n01 = p01 ? lo01 : hi01;
    float2 n10 = p10 ? lo10 : hi10;
    float2 n11 = p11 ? lo11 : hi11;

    float2 e4 = odd ? g00 : n00;
    float2 e5 = odd ? g01 : n01;
    float2 e6 = odd ? g10 : n10;
    float2 e7 = odd ? g11 : n11;

    float omx = 1.f - wx, omy = 1.f - wy, omz = 1.f - wz;

    float c00a = e0.x * omx + e4.x * wx;
    float c01a = e1.x * omx + e5.x * wx;
    float c10a = e2.x * omx + e6.x * wx;
    float c11a = e3.x * omx + e7.x * wx;
    float c0a  = c00a * omy + c10a * wy;
    float c1a  = c01a * omy + c11a * wy;
    float ra   = c0a * omz + c1a * wz;

    float c00b = e0.y * omx + e4.y * wx;
    float c01b = e1.y * omx + e5.y * wx;
    float c10b = e2.y * omx + e6.y * wx;
    float c11b = e3.y * omx + e7.y * wx;
    float c0b  = c00b * omy + c10b * wy;
    float c1b  = c01b * omy + c11b * wy;
    float rb   = c0b * omz + c1b * wz;

    return make_float2(ra, rb);
}

// 4 levels per iteration: 4 independent gather groups in flight before the
// blends consume them (higher MLP to cover L2 latency).
template <typename PointLoader>
__device__ __forceinline__ void encode_point(float px, float py, float pz,
                                             const float* __restrict__ tables,
                                             float4* __restrict__ out4)
{
#pragma unroll
    for (int l = 0; l < N_LEVELS; l += 4) {
        const float2* __restrict__ t0 =
            reinterpret_cast<const float2*>(tables) + (size_t)l * TSIZE;
        const float2* __restrict__ t1 = t0 + TSIZE;
        const float2* __restrict__ t2 = t1 + TSIZE;
        const float2* __restrict__ t3 = t2 + TSIZE;

        float2 r0 = encode_level(px, py, pz, t0, c_res[l]);
        float2 r1 = encode_level(px, py, pz, t1, c_res[l + 1]);
        float2 r2 = encode_level(px, py, pz, t2, c_res[l + 2]);
        float2 r3 = encode_level(px, py, pz, t3, c_res[l + 3]);

        __stcs(&out4[(l >> 1)],     make_float4(r0.x, r0.y, r1.x, r1.y));
        __stcs(&out4[(l >> 1) + 1], make_float4(r2.x, r2.y, r3.x, r3.y));
    }
}

struct Dummy {};

__global__ void __launch_bounds__(256)
encode_sorted_kernel(const float* __restrict__ tables,
                     float* __restrict__ out,
                     int n)
{
    int i = blockIdx.x * blockDim.x + threadIdx.x;
    if (i >= n) return;

    float4 s = g_scratch[i];
    int id = __float_as_int(s.w);
    float4* __restrict__ out4 =
        reinterpret_cast<float4*>(out) + (size_t)id * (N_LEVELS / 2);

    encode_point<Dummy>(s.x, s.y, s.z, tables, out4);
}

// Fallback (n > CAP): encode directly from x in input order.
__global__ void __launch_bounds__(256)
encode_direct_kernel(const float* __restrict__ x,
                     const float* __restrict__ tables,
                     float* __restrict__ out,
                     int n)
{
    int p = blockIdx.x * blockDim.x + threadIdx.x;
    if (p >= n) return;

    float4* __restrict__ out4 =
        reinterpret_cast<float4*>(out) + (size_t)p * (N_LEVELS / 2);
    encode_point<Dummy>(x[3 * p], x[3 * p + 1], x[3 * p + 2], tables, out4);
}

extern "C" void kernel_launch(void* const* d_in, const int* in_sizes, int n_in,
                              void* d_out, int out_size)
{
    const float* x      = (const float*)d_in[0];
    const float* tables = (const float*)d_in[1];
    float* out          = (float*)d_out;

    int n = in_sizes[0] / 3;
    int threads = 256;
    int blocks = (n + threads - 1) / threads;

    if (n <= CAP) {
        zero_hist_kernel<<<(NBUCKETS + 1023) / 1024, 1024>>>();
        hist_kernel<<<blocks, threads>>>(x, n);
        prefix_kernel<<<1, 1024>>>();
        scatter_kernel<<<blocks, threads>>>(x, n);
        encode_sorted_kernel<<<blocks, threads>>>(tables, out, n);
    } else {
        encode_direct_kernel<<<blocks, threads>>>(x, tables, out, n);
    }
}